// round 11
// baseline (speedup 1.0000x reference)
#include <cuda_runtime.h>
#include <cuda_bf16.h>
#include <cstdio>
#include <cstdint>

// ---------------------------------------------------------------------------
// Problem constants
//   N=32, T=64, D=16, F=512
//   obj rows M0 = 32768, graphs G = 2048
// ---------------------------------------------------------------------------
#define M0 32768
#define GNUM 2048

// Scratch (device globals; allocation-free)
__device__ float g_obj[32768 * 512];   // relu(object_fc), with act overwrite
__device__ float g_TT [32768 * 64];    // obj @ [gc1_W | gc3_W]
__device__ float g_Wcat[512 * 64];     // concat(gc1_W, gc3_W)
__device__ float g_Z  [2048 * 64];     // [z2 | z4] per graph
__device__ float g_OM [2048 * 512];    // mean over D of obj per graph
__device__ float g_H  [2048 * 512];    // relu(feat)
__device__ float g_C  [2048 * 1024];   // relu(fc1)
__device__ float g_CB [32 * 1024];     // mean over T of g_C
__device__ float g_zero64[64];         // zero bias (zero-initialized)

// ---------------------------------------------------------------------------
// Generic tiled SGEMM: C[M,N](ldc) = epi(A[M,K] @ B[K,N] + bias)
// All dims assumed multiples of tile sizes (true for every call here).
// ---------------------------------------------------------------------------
template <int BM, int BN, int BK, int TM, int TN>
__global__ __launch_bounds__(256) void sgemm_k(
    const float* __restrict__ A, const float* __restrict__ B,
    const float* __restrict__ bias, float* __restrict__ C,
    int M, int N, int K, int ldc, int do_relu)
{
    constexpr int NT = (BM / TM) * (BN / TN);
    static_assert(NT == 256, "expect 256 threads");
    __shared__ float As[BK][BM];
    __shared__ float Bs[BK][BN];

    const int tid = threadIdx.x;
    const int tx = tid % (BN / TN);
    const int ty = tid / (BN / TN);
    const int rowBase = blockIdx.y * BM;
    const int colBase = blockIdx.x * BN;

    const float* Ablk = A + (size_t)rowBase * K;
    const float* Bblk = B + colBase;

    float acc[TM][TN];
#pragma unroll
    for (int m = 0; m < TM; m++)
#pragma unroll
        for (int n = 0; n < TN; n++) acc[m][n] = 0.f;

    for (int k0 = 0; k0 < K; k0 += BK) {
        // Load A tile (BM x BK), transpose into As[k][row]
#pragma unroll
        for (int idx = tid; idx < BM * BK / 4; idx += NT) {
            int r  = idx / (BK / 4);
            int kq = idx % (BK / 4);
            float4 v = *(const float4*)(Ablk + (size_t)r * K + k0 + kq * 4);
            As[kq * 4 + 0][r] = v.x;
            As[kq * 4 + 1][r] = v.y;
            As[kq * 4 + 2][r] = v.z;
            As[kq * 4 + 3][r] = v.w;
        }
        // Load B tile (BK x BN)
#pragma unroll
        for (int idx = tid; idx < BK * BN / 4; idx += NT) {
            int kk = idx / (BN / 4);
            int nq = idx % (BN / 4);
            *(float4*)&Bs[kk][nq * 4] =
                *(const float4*)(Bblk + (size_t)(k0 + kk) * N + nq * 4);
        }
        __syncthreads();

#pragma unroll
        for (int k = 0; k < BK; k++) {
            float rm[TM], rn[TN];
#pragma unroll
            for (int m = 0; m < TM; m++) rm[m] = As[k][ty * TM + m];
#pragma unroll
            for (int n = 0; n < TN; n++) rn[n] = Bs[k][tx * TN + n];
#pragma unroll
            for (int m = 0; m < TM; m++)
#pragma unroll
                for (int n = 0; n < TN; n++) acc[m][n] += rm[m] * rn[n];
        }
        __syncthreads();
    }

#pragma unroll
    for (int m = 0; m < TM; m++) {
        int row = rowBase + ty * TM + m;
#pragma unroll
        for (int n = 0; n < TN; n++) {
            int col = colBase + tx * TN + n;
            float v = acc[m][n] + bias[col];
            if (do_relu) v = fmaxf(v, 0.f);
            C[(size_t)row * ldc + col] = v;
        }
    }
}

// ---------------------------------------------------------------------------
// Concat gc1_W [512,32] | gc3_W [512,32] -> g_Wcat [512,64]
// ---------------------------------------------------------------------------
__global__ void concat_w_k(const float* __restrict__ g1,
                           const float* __restrict__ g3)
{
    int idx = blockIdx.x * 256 + threadIdx.x;
    if (idx < 512 * 64) {
        int k = idx >> 6, c = idx & 63;
        g_Wcat[idx] = (c < 32) ? g1[k * 32 + c] : g3[k * 32 + (c - 32)];
    }
}

// ---------------------------------------------------------------------------
// Per-graph kernel P1: one block per graph (2048 blocks, 256 threads).
//   - omean = mean over D of x
//   - adj   = normalized softmax-similarity adjacency from s = x x^T
//   - x1pre = relu(adj @ T1 + b1), y2 = relu(adj @ T3 + b3)
//   - adj_hat3 from y2 ; w2 = colmean(adj), w4 = colmean(adj_hat3)
//   - z2 = w2^T x1pre, z4 = w4^T y2   -> g_Z
// SMEM pool reuse: XS (16x513) dies after s, reused for T1/T3/X1P/Y2.
// ---------------------------------------------------------------------------
__global__ __launch_bounds__(256) void graph_p1_k(
    const float* __restrict__ b1, const float* __restrict__ b3)
{
    const int g = blockIdx.x;
    const int tid = threadIdx.x;

    __shared__ float POOL[16 * 513];      // XS; later T1S/T3S/X1P/Y2S
    __shared__ float PS[8 * 16 * 17];     // s partials
    __shared__ float sA[16 * 17];         // s -> a -> adj
    __shared__ float sB[16 * 17];         // y22 -> adj3 -> adj_hat3
    __shared__ float rr[16], dv[16], w2s[16], w4s[16], nr[16];

    const float* xg = g_obj + (size_t)g * 8192;
    for (int idx = tid; idx < 8192; idx += 256)
        POOL[(idx >> 9) * 513 + (idx & 511)] = xg[idx];
    __syncthreads();

    // omean (reads XS)
    for (int c = tid; c < 512; c += 256) {
        float s = 0.f;
#pragma unroll
        for (int d = 0; d < 16; d++) s += POOL[d * 513 + c];
        g_OM[(size_t)g * 512 + c] = s * 0.0625f;
    }

    // s = x x^T : 4x4 register tiles, K split by 8 (128 active threads)
    if (tid < 128) {
        int kc = tid >> 4;
        int tile = tid & 15;
        int ti = (tile >> 2) * 4, tj = (tile & 3) * 4;
        float acc[4][4];
#pragma unroll
        for (int m = 0; m < 4; m++)
#pragma unroll
            for (int n = 0; n < 4; n++) acc[m][n] = 0.f;
        int k0 = kc * 64;
        for (int k = k0; k < k0 + 64; k++) {
            float a0 = POOL[(ti + 0) * 513 + k];
            float a1 = POOL[(ti + 1) * 513 + k];
            float a2 = POOL[(ti + 2) * 513 + k];
            float a3 = POOL[(ti + 3) * 513 + k];
            float b0 = POOL[(tj + 0) * 513 + k];
            float c1 = POOL[(tj + 1) * 513 + k];
            float c2 = POOL[(tj + 2) * 513 + k];
            float c3 = POOL[(tj + 3) * 513 + k];
            acc[0][0] += a0 * b0; acc[0][1] += a0 * c1; acc[0][2] += a0 * c2; acc[0][3] += a0 * c3;
            acc[1][0] += a1 * b0; acc[1][1] += a1 * c1; acc[1][2] += a1 * c2; acc[1][3] += a1 * c3;
            acc[2][0] += a2 * b0; acc[2][1] += a2 * c1; acc[2][2] += a2 * c2; acc[2][3] += a2 * c3;
            acc[3][0] += a3 * b0; acc[3][1] += a3 * c1; acc[3][2] += a3 * c2; acc[3][3] += a3 * c3;
        }
#pragma unroll
        for (int m = 0; m < 4; m++)
#pragma unroll
            for (int n = 0; n < 4; n++)
                PS[kc * 272 + (ti + m) * 17 + (tj + n)] = acc[m][n];
    }
    __syncthreads();
    // ------- XS dead from here -------

    // Load T1/T3 into POOL (T1S at 0, T3S at 528; X1P at 1056, Y2S at 1584)
    {
        const float* ttg = g_TT + (size_t)g * 1024;
        for (int idx = tid; idx < 1024; idx += 256) {
            int r = idx >> 6, c = idx & 63;
            float v = ttg[idx];
            if (c < 32) POOL[r * 33 + c] = v;
            else        POOL[528 + r * 33 + (c - 32)] = v;
        }
    }
    // Reduce PS -> sA (raw similarity s)
    {
        int i = tid >> 4, j = tid & 15;
        float s = 0.f;
#pragma unroll
        for (int kc = 0; kc < 8; kc++) s += PS[kc * 272 + i * 17 + j];
        sA[i * 17 + j] = s;
    }
    __syncthreads();

    if (tid < 16) {
        float m = -3.4e38f;
        for (int j = 0; j < 16; j++) m = fmaxf(m, sA[tid * 17 + j]);
        rr[tid] = m;
    }
    __syncthreads();
    { int i = tid >> 4, j = tid & 15; sA[i * 17 + j] = expf(sA[i * 17 + j] - rr[i]); }
    __syncthreads();
    if (tid < 16) {
        float s = 0.f;
        for (int j = 0; j < 16; j++) s += sA[tid * 17 + j];
        dv[tid] = rsqrtf(s);
    }
    __syncthreads();
    { int i = tid >> 4, j = tid & 15; sA[i * 17 + j] *= dv[i] * dv[j]; }
    __syncthreads();

    // w2 = colmean(adj)
    if (tid < 16) {
        float s = 0.f;
        for (int i = 0; i < 16; i++) s += sA[i * 17 + tid];
        w2s[tid] = s * 0.0625f;
    }
    // x1pre = relu(adj@T1 + b1); y2 = relu(adj@T3 + b3)
    for (int o = tid; o < 1024; o += 256) {
        int which = o >> 9, r = (o >> 5) & 15, c = o & 31;
        const float* Ts = which ? (POOL + 528) : POOL;
        float acc = which ? b3[c] : b1[c];
#pragma unroll
        for (int j = 0; j < 16; j++) acc += sA[r * 17 + j] * Ts[j * 33 + c];
        acc = fmaxf(acc, 0.f);
        (which ? (POOL + 1584) : (POOL + 1056))[r * 33 + c] = acc;
    }
    __syncthreads();

    // y22 = y2 y2^T
    {
        int i = tid >> 4, j = tid & 15;
        const float* Y2S = POOL + 1584;
        float acc = 0.f;
#pragma unroll
        for (int k = 0; k < 32; k++) acc += Y2S[i * 33 + k] * Y2S[j * 33 + k];
        sB[i * 17 + j] = acc;
    }
    __syncthreads();
    if (tid < 16) {
        float s = 0.f;
        for (int j = 0; j < 16; j++) { float v = sB[tid * 17 + j]; s += v * v; }
        nr[tid] = sqrtf(s);
    }
    __syncthreads();
    { int i = tid >> 4, j = tid & 15; sB[i * 17 + j] = 1.f + sB[i * 17 + j] / (nr[i] * nr[j]); }
    __syncthreads();
    if (tid < 16) {
        float s = 0.f;
        for (int j = 0; j < 16; j++) s += sB[tid * 17 + j];
        dv[tid] = rsqrtf(s);
    }
    __syncthreads();
    { int i = tid >> 4, j = tid & 15; sB[i * 17 + j] *= dv[i] * dv[j]; }
    __syncthreads();
    if (tid < 16) {
        float s = 0.f;
        for (int i = 0; i < 16; i++) s += sB[i * 17 + tid];
        w4s[tid] = s * 0.0625f;
    }
    __syncthreads();

    // z2 / z4
    if (tid < 64) {
        int which = tid >> 5, c = tid & 31;
        const float* V = which ? (POOL + 1584) : (POOL + 1056);
        const float* w = which ? w4s : w2s;
        float acc = 0.f;
#pragma unroll
        for (int j = 0; j < 16; j++) acc += w[j] * V[j * 33 + c];
        g_Z[(size_t)g * 64 + tid] = acc;
    }
}

// ---------------------------------------------------------------------------
// P2: h[g,c] = relu(0.5*omean + 0.25*(z2@gc2_W + z4@gc4_W + b2 + b4))
// 8 graphs per block to amortize weight reads.
// ---------------------------------------------------------------------------
__global__ __launch_bounds__(512) void graph_p2_k(
    const float* __restrict__ gc2_W, const float* __restrict__ b2,
    const float* __restrict__ gc4_W, const float* __restrict__ b4)
{
    const int g0 = blockIdx.x * 8;
    const int tid = threadIdx.x;
    __shared__ float zs[8][64];
    zs[tid >> 6][tid & 63] = g_Z[(size_t)g0 * 64 + tid];
    __syncthreads();

    const int c = tid;  // 512 columns
    float acc[8];
    float base = b2[c] + b4[c];
#pragma unroll
    for (int gg = 0; gg < 8; gg++) acc[gg] = base;
#pragma unroll
    for (int k = 0; k < 32; k++) {
        float w = gc2_W[k * 512 + c];
#pragma unroll
        for (int gg = 0; gg < 8; gg++) acc[gg] += zs[gg][k] * w;
    }
#pragma unroll
    for (int k = 0; k < 32; k++) {
        float w = gc4_W[k * 512 + c];
#pragma unroll
        for (int gg = 0; gg < 8; gg++) acc[gg] += zs[gg][32 + k] * w;
    }
#pragma unroll
    for (int gg = 0; gg < 8; gg++) {
        float h = 0.5f * g_OM[(size_t)(g0 + gg) * 512 + c] + 0.25f * acc[gg];
        g_H[(size_t)(g0 + gg) * 512 + c] = fmaxf(h, 0.f);
    }
}

// ---------------------------------------------------------------------------
// Mean over T: CB[n,c] = mean_t C[n*64+t, c]
// ---------------------------------------------------------------------------
__global__ void reduce_t_k()
{
    int n = blockIdx.x;
    int c = blockIdx.y * 256 + threadIdx.x;
    const float* p = g_C + (size_t)n * 64 * 1024 + c;
    float s = 0.f;
#pragma unroll
    for (int t = 0; t < 64; t++) s += p[t * 1024];
    g_CB[n * 1024 + c] = s * (1.f / 64.f);
}

// ---------------------------------------------------------------------------
// Classifier: out[n,c] = CB[n,:] @ clf_W[:,c] + clf_b[c]
// ---------------------------------------------------------------------------
__global__ __launch_bounds__(512) void clf_k(
    const float* __restrict__ W, const float* __restrict__ b,
    float* __restrict__ out)
{
    int n = blockIdx.x;
    int tid = threadIdx.x;
    __shared__ float cb[1024];
    cb[tid]       = g_CB[n * 1024 + tid];
    cb[tid + 512] = g_CB[n * 1024 + tid + 512];
    __syncthreads();
    if (tid < 500) {
        float acc = b[tid];
        for (int k = 0; k < 1024; k++) acc += cb[k] * W[k * 500 + tid];
        out[n * 500 + tid] = acc;
    }
}

// ---------------------------------------------------------------------------
// kernel_launch
// ---------------------------------------------------------------------------
extern "C" void kernel_launch(void* const* d_in, const int* in_sizes, int n_in,
                              void* d_out, int out_size)
{
    const float* object_raw = (const float*)d_in[0];
    const float* action_raw = (const float*)d_in[1];
    const float* W_obj = (const float*)d_in[2];
    const float* b_obj = (const float*)d_in[3];
    const float* W_act = (const float*)d_in[4];
    const float* b_act = (const float*)d_in[5];
    const float* gc1_W = (const float*)d_in[6];
    const float* gc1_b = (const float*)d_in[7];
    const float* gc2_W = (const float*)d_in[8];
    const float* gc2_b = (const float*)d_in[9];
    const float* gc3_W = (const float*)d_in[10];
    const float* gc3_b = (const float*)d_in[11];
    const float* gc4_W = (const float*)d_in[12];
    const float* gc4_b = (const float*)d_in[13];
    const float* fc1_W = (const float*)d_in[14];
    const float* fc1_b = (const float*)d_in[15];
    const float* clf_W = (const float*)d_in[16];
    const float* clf_b = (const float*)d_in[17];
    float* out = (float*)d_out;

    float *p_obj, *p_TT, *p_Wcat, *p_H, *p_C, *p_zero;
    cudaGetSymbolAddress((void**)&p_obj,  g_obj);
    cudaGetSymbolAddress((void**)&p_TT,   g_TT);
    cudaGetSymbolAddress((void**)&p_Wcat, g_Wcat);
    cudaGetSymbolAddress((void**)&p_H,    g_H);
    cudaGetSymbolAddress((void**)&p_C,    g_C);
    cudaGetSymbolAddress((void**)&p_zero, g_zero64);

    // 1) obj = relu(object_raw @ W_obj + b_obj)   [32768, 512]
    sgemm_k<128, 128, 16, 8, 8><<<dim3(512 / 128, M0 / 128), 256>>>(
        object_raw, W_obj, b_obj, p_obj, M0, 512, 512, 512, 1);

    // 2) act = relu(action_raw @ W_act + b_act) written into obj rows 16g+8
    sgemm_k<128, 128, 16, 8, 8><<<dim3(512 / 128, 2048 / 128), 256>>>(
        action_raw, W_act, b_act, p_obj + 8 * 512, 2048, 512, 512, 16 * 512, 1);

    // 3) W concat + TT = obj @ [gc1_W | gc3_W]   [32768, 64]
    concat_w_k<<<(512 * 64 + 255) / 256, 256>>>(gc1_W, gc3_W);
    sgemm_k<128, 64, 16, 8, 4><<<dim3(1, M0 / 128), 256>>>(
        p_obj, p_Wcat, p_zero, p_TT, M0, 64, 512, 64, 0);

    // 4) per-graph: adjacency, branch pre-activations, z2/z4, omean
    graph_p1_k<<<GNUM, 256>>>(gc1_b, gc3_b);

    // 5) h = relu(feat)
    graph_p2_k<<<GNUM / 8, 512>>>(gc2_W, gc2_b, gc4_W, gc4_b);

    // 6) c = relu(h @ fc1_W + fc1_b)   [2048, 1024]
    sgemm_k<128, 128, 16, 8, 8><<<dim3(1024 / 128, 2048 / 128), 256>>>(
        p_H, fc1_W, fc1_b, p_C, 2048, 1024, 512, 1024, 1);

    // 7) mean over T, 8) classifier
    reduce_t_k<<<dim3(32, 4), 256>>>();
    clf_k<<<32, 512>>>(clf_W, clf_b, out);
}

// round 15
// speedup vs baseline: 1.8137x; 1.8137x over previous
#include <cuda_runtime.h>
#include <cstdint>

// ---------------------------------------------------------------------------
// Problem constants: N=32, T=64, D=16, F=512 ; obj rows M0=32768, graphs=2048
// ---------------------------------------------------------------------------
#define M0 32768
#define GNUM 2048

// Scratch (device globals; allocation-free)
__device__ float g_obj[32768 * 512];
__device__ float g_TT [32768 * 64];
__device__ float g_Z  [2048 * 64];
__device__ float g_OM [2048 * 512];
__device__ float g_H  [2048 * 512];
__device__ float g_C  [2048 * 1024];
__device__ float g_CB [32 * 1024];
__device__ float g_zero64[64];
// transposed weights (B operands are [N, K] k-major)
__device__ float g_WobjT[512 * 512];
__device__ float g_WactT[512 * 512];
__device__ float g_fc1T [1024 * 512];
__device__ float g_WcatT[64 * 512];

// ---------------------------------------------------------------------------
// tf32 helpers (legacy tensor-core path: mma.sync, valid on plain sm_103)
// ---------------------------------------------------------------------------
__device__ __forceinline__ float f2tf32f(float x) {
    uint32_t u; asm("cvt.rna.tf32.f32 %0, %1;" : "=r"(u) : "f"(x));
    return __uint_as_float(u);
}
__device__ __forceinline__ void mma8(float* c, const uint32_t* a, const uint32_t* b) {
    asm volatile(
        "mma.sync.aligned.m16n8k8.row.col.f32.tf32.tf32.f32 "
        "{%0,%1,%2,%3}, {%4,%5,%6,%7}, {%8,%9}, {%0,%1,%2,%3};"
        : "+f"(c[0]), "+f"(c[1]), "+f"(c[2]), "+f"(c[3])
        : "r"(a[0]), "r"(a[1]), "r"(a[2]), "r"(a[3]), "r"(b[0]), "r"(b[1]));
}

// ---------------------------------------------------------------------------
// tf32 tensor-core GEMM:  C[row, col] = epi( A[M,K] @ BT[N,K]^T + bias )
// CTA tile 128 x BN, BK=32, double-buffered SMEM (pad stride 36 floats).
// 256 threads = 8 warps in 4(m) x 2(n); warp tile 32 x (BN/2).
// grid = (N/BN, M/128). Requires K%32==0, M%128==0, N%BN==0.
// ---------------------------------------------------------------------------
template <int BN>
__global__ __launch_bounds__(256) void mmagemm_k(
    const float* __restrict__ A, const float* __restrict__ BT,
    const float* __restrict__ bias, float* __restrict__ C,
    int K, int ldc, int do_relu)
{
    constexpr int LDP = 36;                 // padded row stride (floats)
    constexpr int ASZ = 128 * LDP;          // one A buffer
    constexpr int BSZ = BN * LDP;           // one B buffer
    constexpr int NT  = BN / 16;            // n-tiles per warp (8 or 4)
    constexpr int NB4 = (BN * 8) / 256;     // B float4 per thread per chunk

    extern __shared__ float sm[];
    float* Abuf[2] = { sm, sm + ASZ };
    float* Bbuf[2] = { sm + 2 * ASZ, sm + 2 * ASZ + BSZ };

    const int tid  = threadIdx.x;
    const int lane = tid & 31;
    const int wid  = tid >> 5;
    const int warpM = (wid & 3) * 32;
    const int warpN = (wid >> 2) * (BN / 2);
    const int rowBase = blockIdx.y * 128;
    const int colBase = blockIdx.x * BN;
    const int qr = lane >> 2, qk = lane & 3;

    float acc[2][NT][4];
#pragma unroll
    for (int mt = 0; mt < 2; mt++)
#pragma unroll
        for (int nt = 0; nt < NT; nt++)
#pragma unroll
            for (int q = 0; q < 4; q++) acc[mt][nt][q] = 0.f;

    float4 stA[4], stB[NB4];

    auto g_load = [&](int k0) {
#pragma unroll
        for (int it = 0; it < 4; it++) {
            int e = it * 256 + tid, r = e >> 3, q = e & 7;
            stA[it] = *(const float4*)(A + (size_t)(rowBase + r) * K + k0 + q * 4);
        }
#pragma unroll
        for (int it = 0; it < NB4; it++) {
            int e = it * 256 + tid, r = e >> 3, q = e & 7;
            stB[it] = *(const float4*)(BT + (size_t)(colBase + r) * K + k0 + q * 4);
        }
    };
    auto s_store = [&](int b) {
#pragma unroll
        for (int it = 0; it < 4; it++) {
            int e = it * 256 + tid, r = e >> 3, q = e & 7;
            float4 v = { f2tf32f(stA[it].x), f2tf32f(stA[it].y),
                         f2tf32f(stA[it].z), f2tf32f(stA[it].w) };
            *(float4*)(Abuf[b] + r * LDP + q * 4) = v;
        }
#pragma unroll
        for (int it = 0; it < NB4; it++) {
            int e = it * 256 + tid, r = e >> 3, q = e & 7;
            float4 v = { f2tf32f(stB[it].x), f2tf32f(stB[it].y),
                         f2tf32f(stB[it].z), f2tf32f(stB[it].w) };
            *(float4*)(Bbuf[b] + r * LDP + q * 4) = v;
        }
    };
    auto compute = [&](int b) {
        const float* Ab = Abuf[b];
        const float* Bb = Bbuf[b];
#pragma unroll
        for (int kk = 0; kk < 4; kk++) {
            uint32_t af[2][4], bf[NT][2];
#pragma unroll
            for (int mt = 0; mt < 2; mt++) {
                int r0 = warpM + mt * 16 + qr;
                af[mt][0] = __float_as_uint(Ab[(r0)     * LDP + kk * 8 + qk]);
                af[mt][1] = __float_as_uint(Ab[(r0 + 8) * LDP + kk * 8 + qk]);
                af[mt][2] = __float_as_uint(Ab[(r0)     * LDP + kk * 8 + qk + 4]);
                af[mt][3] = __float_as_uint(Ab[(r0 + 8) * LDP + kk * 8 + qk + 4]);
            }
#pragma unroll
            for (int nt = 0; nt < NT; nt++) {
                int n0 = warpN + nt * 8 + qr;
                bf[nt][0] = __float_as_uint(Bb[n0 * LDP + kk * 8 + qk]);
                bf[nt][1] = __float_as_uint(Bb[n0 * LDP + kk * 8 + qk + 4]);
            }
#pragma unroll
            for (int mt = 0; mt < 2; mt++)
#pragma unroll
                for (int nt = 0; nt < NT; nt++)
                    mma8(acc[mt][nt], af[mt], bf[nt]);
        }
    };

    const int nc = K >> 5;
    g_load(0);
    s_store(0);
    __syncthreads();
    for (int i = 0; i < nc; i++) {
        if (i + 1 < nc) g_load((i + 1) << 5);
        compute(i & 1);
        if (i + 1 < nc) s_store((i + 1) & 1);
        __syncthreads();
    }

    // epilogue: bias + optional relu, float2 stores
#pragma unroll
    for (int mt = 0; mt < 2; mt++) {
        int row = rowBase + warpM + mt * 16 + qr;
#pragma unroll
        for (int nt = 0; nt < NT; nt++) {
            int col = colBase + warpN + nt * 8 + qk * 2;
            float b0 = bias[col], b1 = bias[col + 1];
            float2 v0 = { acc[mt][nt][0] + b0, acc[mt][nt][1] + b1 };
            float2 v1 = { acc[mt][nt][2] + b0, acc[mt][nt][3] + b1 };
            if (do_relu) {
                v0.x = fmaxf(v0.x, 0.f); v0.y = fmaxf(v0.y, 0.f);
                v1.x = fmaxf(v1.x, 0.f); v1.y = fmaxf(v1.y, 0.f);
            }
            *(float2*)(C + (size_t)row * ldc + col)       = v0;
            *(float2*)(C + (size_t)(row + 8) * ldc + col) = v1;
        }
    }
}

// ---------------------------------------------------------------------------
// Transpose: out[c*K + k] = in[k*N + c]   (K, N multiples of 32)
// ---------------------------------------------------------------------------
__global__ void transpose_k(const float* __restrict__ in, float* __restrict__ out,
                            int K, int N)
{
    __shared__ float t[32][33];
    int k0 = blockIdx.y * 32, c0 = blockIdx.x * 32;
    for (int r = threadIdx.y; r < 32; r += 8)
        t[r][threadIdx.x] = in[(size_t)(k0 + r) * N + c0 + threadIdx.x];
    __syncthreads();
    for (int r = threadIdx.y; r < 32; r += 8)
        out[(size_t)(c0 + r) * K + k0 + threadIdx.x] = t[threadIdx.x][r];
}

// WcatT[c][k]: c<32 -> gc1_W[k,c], else gc3_W[k,c-32]   -> [64,512]
__global__ void concat_wt_k(const float* __restrict__ g1, const float* __restrict__ g3)
{
    int idx = blockIdx.x * 256 + threadIdx.x;   // 64*512
    if (idx < 64 * 512) {
        int c = idx >> 9, k = idx & 511;
        g_WcatT[idx] = (c < 32) ? g1[k * 32 + c] : g3[k * 32 + (c - 32)];
    }
}

// ---------------------------------------------------------------------------
// Per-graph kernel P1: adjacency, branches, z2/z4, omean (known-good)
// ---------------------------------------------------------------------------
__global__ __launch_bounds__(256) void graph_p1_k(
    const float* __restrict__ b1, const float* __restrict__ b3)
{
    const int g = blockIdx.x;
    const int tid = threadIdx.x;

    __shared__ float POOL[16 * 513];
    __shared__ float PS[8 * 16 * 17];
    __shared__ float sA[16 * 17];
    __shared__ float sB[16 * 17];
    __shared__ float rr[16], dv[16], w2s[16], w4s[16], nr[16];

    const float* xg = g_obj + (size_t)g * 8192;
    for (int idx = tid; idx < 8192; idx += 256)
        POOL[(idx >> 9) * 513 + (idx & 511)] = xg[idx];
    __syncthreads();

    for (int c = tid; c < 512; c += 256) {
        float s = 0.f;
#pragma unroll
        for (int d = 0; d < 16; d++) s += POOL[d * 513 + c];
        g_OM[(size_t)g * 512 + c] = s * 0.0625f;
    }

    if (tid < 128) {
        int kc = tid >> 4;
        int tile = tid & 15;
        int ti = (tile >> 2) * 4, tj = (tile & 3) * 4;
        float acc[4][4];
#pragma unroll
        for (int m = 0; m < 4; m++)
#pragma unroll
            for (int n = 0; n < 4; n++) acc[m][n] = 0.f;
        int k0 = kc * 64;
        for (int k = k0; k < k0 + 64; k++) {
            float a0 = POOL[(ti + 0) * 513 + k];
            float a1 = POOL[(ti + 1) * 513 + k];
            float a2 = POOL[(ti + 2) * 513 + k];
            float a3 = POOL[(ti + 3) * 513 + k];
            float b0 = POOL[(tj + 0) * 513 + k];
            float c1 = POOL[(tj + 1) * 513 + k];
            float c2 = POOL[(tj + 2) * 513 + k];
            float c3 = POOL[(tj + 3) * 513 + k];
            acc[0][0] += a0 * b0; acc[0][1] += a0 * c1; acc[0][2] += a0 * c2; acc[0][3] += a0 * c3;
            acc[1][0] += a1 * b0; acc[1][1] += a1 * c1; acc[1][2] += a1 * c2; acc[1][3] += a1 * c3;
            acc[2][0] += a2 * b0; acc[2][1] += a2 * c1; acc[2][2] += a2 * c2; acc[2][3] += a2 * c3;
            acc[3][0] += a3 * b0; acc[3][1] += a3 * c1; acc[3][2] += a3 * c2; acc[3][3] += a3 * c3;
        }
#pragma unroll
        for (int m = 0; m < 4; m++)
#pragma unroll
            for (int n = 0; n < 4; n++)
                PS[kc * 272 + (ti + m) * 17 + (tj + n)] = acc[m][n];
    }
    __syncthreads();

    {
        const float* ttg = g_TT + (size_t)g * 1024;
        for (int idx = tid; idx < 1024; idx += 256) {
            int r = idx >> 6, c = idx & 63;
            float v = ttg[idx];
            if (c < 32) POOL[r * 33 + c] = v;
            else        POOL[528 + r * 33 + (c - 32)] = v;
        }
    }
    {
        int i = tid >> 4, j = tid & 15;
        float s = 0.f;
#pragma unroll
        for (int kc = 0; kc < 8; kc++) s += PS[kc * 272 + i * 17 + j];
        sA[i * 17 + j] = s;
    }
    __syncthreads();

    if (tid < 16) {
        float m = -3.4e38f;
        for (int j = 0; j < 16; j++) m = fmaxf(m, sA[tid * 17 + j]);
        rr[tid] = m;
    }
    __syncthreads();
    { int i = tid >> 4, j = tid & 15; sA[i * 17 + j] = expf(sA[i * 17 + j] - rr[i]); }
    __syncthreads();
    if (tid < 16) {
        float s = 0.f;
        for (int j = 0; j < 16; j++) s += sA[tid * 17 + j];
        dv[tid] = rsqrtf(s);
    }
    __syncthreads();
    { int i = tid >> 4, j = tid & 15; sA[i * 17 + j] *= dv[i] * dv[j]; }
    __syncthreads();

    if (tid < 16) {
        float s = 0.f;
        for (int i = 0; i < 16; i++) s += sA[i * 17 + tid];
        w2s[tid] = s * 0.0625f;
    }
    for (int o = tid; o < 1024; o += 256) {
        int which = o >> 9, r = (o >> 5) & 15, c = o & 31;
        const float* Ts = which ? (POOL + 528) : POOL;
        float acc = which ? b3[c] : b1[c];
#pragma unroll
        for (int j = 0; j < 16; j++) acc += sA[r * 17 + j] * Ts[j * 33 + c];
        acc = fmaxf(acc, 0.f);
        (which ? (POOL + 1584) : (POOL + 1056))[r * 33 + c] = acc;
    }
    __syncthreads();

    {
        int i = tid >> 4, j = tid & 15;
        const float* Y2S = POOL + 1584;
        float acc = 0.f;
#pragma unroll
        for (int k = 0; k < 32; k++) acc += Y2S[i * 33 + k] * Y2S[j * 33 + k];
        sB[i * 17 + j] = acc;
    }
    __syncthreads();
    if (tid < 16) {
        float s = 0.f;
        for (int j = 0; j < 16; j++) { float v = sB[tid * 17 + j]; s += v * v; }
        nr[tid] = sqrtf(s);
    }
    __syncthreads();
    { int i = tid >> 4, j = tid & 15; sB[i * 17 + j] = 1.f + sB[i * 17 + j] / (nr[i] * nr[j]); }
    __syncthreads();
    if (tid < 16) {
        float s = 0.f;
        for (int j = 0; j < 16; j++) s += sB[tid * 17 + j];
        dv[tid] = rsqrtf(s);
    }
    __syncthreads();
    { int i = tid >> 4, j = tid & 15; sB[i * 17 + j] *= dv[i] * dv[j]; }
    __syncthreads();
    if (tid < 16) {
        float s = 0.f;
        for (int i = 0; i < 16; i++) s += sB[i * 17 + tid];
        w4s[tid] = s * 0.0625f;
    }
    __syncthreads();

    if (tid < 64) {
        int which = tid >> 5, c = tid & 31;
        const float* V = which ? (POOL + 1584) : (POOL + 1056);
        const float* w = which ? w4s : w2s;
        float acc = 0.f;
#pragma unroll
        for (int j = 0; j < 16; j++) acc += w[j] * V[j * 33 + c];
        g_Z[(size_t)g * 64 + tid] = acc;
    }
}

// ---------------------------------------------------------------------------
// P2: h = relu(0.5*omean + 0.25*(z2@gc2_W + z4@gc4_W + b2 + b4))
// ---------------------------------------------------------------------------
__global__ __launch_bounds__(512) void graph_p2_k(
    const float* __restrict__ gc2_W, const float* __restrict__ b2,
    const float* __restrict__ gc4_W, const float* __restrict__ b4)
{
    const int g0 = blockIdx.x * 8;
    const int tid = threadIdx.x;
    __shared__ float zs[8][64];
    zs[tid >> 6][tid & 63] = g_Z[(size_t)g0 * 64 + tid];
    __syncthreads();

    const int c = tid;
    float acc[8];
    float base = b2[c] + b4[c];
#pragma unroll
    for (int gg = 0; gg < 8; gg++) acc[gg] = base;
#pragma unroll
    for (int k = 0; k < 32; k++) {
        float w = gc2_W[k * 512 + c];
#pragma unroll
        for (int gg = 0; gg < 8; gg++) acc[gg] += zs[gg][k] * w;
    }
#pragma unroll
    for (int k = 0; k < 32; k++) {
        float w = gc4_W[k * 512 + c];
#pragma unroll
        for (int gg = 0; gg < 8; gg++) acc[gg] += zs[gg][32 + k] * w;
    }
#pragma unroll
    for (int gg = 0; gg < 8; gg++) {
        float h = 0.5f * g_OM[(size_t)(g0 + gg) * 512 + c] + 0.25f * acc[gg];
        g_H[(size_t)(g0 + gg) * 512 + c] = fmaxf(h, 0.f);
    }
}

__global__ void reduce_t_k()
{
    int n = blockIdx.x;
    int c = blockIdx.y * 256 + threadIdx.x;
    const float* p = g_C + (size_t)n * 64 * 1024 + c;
    float s = 0.f;
#pragma unroll
    for (int t = 0; t < 64; t++) s += p[t * 1024];
    g_CB[n * 1024 + c] = s * (1.f / 64.f);
}

__global__ __launch_bounds__(512) void clf_k(
    const float* __restrict__ W, const float* __restrict__ b,
    float* __restrict__ out)
{
    int n = blockIdx.x;
    int tid = threadIdx.x;
    __shared__ float cb[1024];
    cb[tid]       = g_CB[n * 1024 + tid];
    cb[tid + 512] = g_CB[n * 1024 + tid + 512];
    __syncthreads();
    if (tid < 500) {
        float acc = b[tid];
        for (int k = 0; k < 1024; k++) acc += cb[k] * W[k * 500 + tid];
        out[n * 500 + tid] = acc;
    }
}

// ---------------------------------------------------------------------------
// kernel_launch
// ---------------------------------------------------------------------------
extern "C" void kernel_launch(void* const* d_in, const int* in_sizes, int n_in,
                              void* d_out, int out_size)
{
    const float* object_raw = (const float*)d_in[0];
    const float* action_raw = (const float*)d_in[1];
    const float* W_obj = (const float*)d_in[2];
    const float* b_obj = (const float*)d_in[3];
    const float* W_act = (const float*)d_in[4];
    const float* b_act = (const float*)d_in[5];
    const float* gc1_W = (const float*)d_in[6];
    const float* gc1_b = (const float*)d_in[7];
    const float* gc2_W = (const float*)d_in[8];
    const float* gc2_b = (const float*)d_in[9];
    const float* gc3_W = (const float*)d_in[10];
    const float* gc3_b = (const float*)d_in[11];
    const float* gc4_W = (const float*)d_in[12];
    const float* gc4_b = (const float*)d_in[13];
    const float* fc1_W = (const float*)d_in[14];
    const float* fc1_b = (const float*)d_in[15];
    const float* clf_W = (const float*)d_in[16];
    const float* clf_b = (const float*)d_in[17];
    float* out = (float*)d_out;

    float *p_obj, *p_TT, *p_H, *p_C, *p_zero;
    float *p_WobjT, *p_WactT, *p_fc1T, *p_WcatT;
    cudaGetSymbolAddress((void**)&p_obj,   g_obj);
    cudaGetSymbolAddress((void**)&p_TT,    g_TT);
    cudaGetSymbolAddress((void**)&p_H,     g_H);
    cudaGetSymbolAddress((void**)&p_C,     g_C);
    cudaGetSymbolAddress((void**)&p_zero,  g_zero64);
    cudaGetSymbolAddress((void**)&p_WobjT, g_WobjT);
    cudaGetSymbolAddress((void**)&p_WactT, g_WactT);
    cudaGetSymbolAddress((void**)&p_fc1T,  g_fc1T);
    cudaGetSymbolAddress((void**)&p_WcatT, g_WcatT);

    // dynamic SMEM: 2 * (128*36 + BN*36) * 4 bytes
    const int SZ128 = 2 * (128 * 36 + 128 * 36) * 4;   // 73728
    const int SZ64  = 2 * (128 * 36 +  64 * 36) * 4;   // 55296
    cudaFuncSetAttribute(mmagemm_k<128>, cudaFuncAttributeMaxDynamicSharedMemorySize, SZ128);
    cudaFuncSetAttribute(mmagemm_k<64>,  cudaFuncAttributeMaxDynamicSharedMemorySize, SZ64);

    // 0) weight transposes (B operands must be [N, K])
    transpose_k<<<dim3(512 / 32, 512 / 32), dim3(32, 8)>>>(W_obj, p_WobjT, 512, 512);
    transpose_k<<<dim3(512 / 32, 512 / 32), dim3(32, 8)>>>(W_act, p_WactT, 512, 512);
    transpose_k<<<dim3(1024 / 32, 512 / 32), dim3(32, 8)>>>(fc1_W, p_fc1T, 512, 1024);
    concat_wt_k<<<(64 * 512 + 255) / 256, 256>>>(gc1_W, gc3_W);

    // 1) obj = relu(object_raw @ W_obj + b_obj)   [32768, 512]
    mmagemm_k<128><<<dim3(4, M0 / 128), 256, SZ128>>>(
        object_raw, p_WobjT, b_obj, p_obj, 512, 512, 1);

    // 2) act = relu(action_raw @ W_act + b_act) -> obj rows 16g+8 (ldc=8192)
    mmagemm_k<128><<<dim3(4, 16), 256, SZ128>>>(
        action_raw, p_WactT, b_act, p_obj + 8 * 512, 512, 16 * 512, 1);

    // 3) TT = obj @ [gc1_W | gc3_W]   [32768, 64]
    mmagemm_k<64><<<dim3(1, M0 / 128), 256, SZ64>>>(
        p_obj, p_WcatT, p_zero, p_TT, 512, 64, 0);

    // 4) per-graph adjacency / branches / z / omean
    graph_p1_k<<<GNUM, 256>>>(gc1_b, gc3_b);

    // 5) h = relu(feat)
    graph_p2_k<<<GNUM / 8, 512>>>(gc2_W, gc2_b, gc4_W, gc4_b);

    // 6) c = relu(h @ fc1_W + fc1_b)   [2048, 1024]
    mmagemm_k<128><<<dim3(8, 16), 256, SZ128>>>(
        p_H, p_fc1T, fc1_b, p_C, 512, 1024, 1);

    // 7) mean over T, 8) classifier
    reduce_t_k<<<dim3(32, 4), 256>>>();
    clf_k<<<32, 512>>>(clf_W, clf_b, out);
}

// round 16
// speedup vs baseline: 1.8746x; 1.0336x over previous
#include <cuda_runtime.h>
#include <cstdint>

// ---------------------------------------------------------------------------
// Problem constants: N=32, T=64, D=16, F=512 ; obj rows M0=32768, graphs=2048
// ---------------------------------------------------------------------------
#define M0 32768
#define GNUM 2048

// Scratch (device globals; allocation-free)
__device__ float g_obj[32768 * 512];
__device__ float g_TT [32768 * 64];
__device__ float g_Z  [2048 * 64];
__device__ float g_OM [2048 * 512];
__device__ float g_H  [2048 * 512];
__device__ float g_C  [2048 * 1024];
__device__ float g_CB [32 * 1024];
__device__ float g_zero64[64];
// transposed weights (B operands are [N, K] k-major)
__device__ float g_WobjT[512 * 512];
__device__ float g_WactT[512 * 512];
__device__ float g_fc1T [1024 * 512];
__device__ float g_WcatT[64 * 512];

// ---------------------------------------------------------------------------
// tf32 helpers (legacy tensor-core path: mma.sync, valid on plain sm_103)
// ---------------------------------------------------------------------------
__device__ __forceinline__ float f2tf32f(float x) {
    uint32_t u; asm("cvt.rna.tf32.f32 %0, %1;" : "=r"(u) : "f"(x));
    return __uint_as_float(u);
}
__device__ __forceinline__ void mma8(float* c, const uint32_t* a, const uint32_t* b) {
    asm volatile(
        "mma.sync.aligned.m16n8k8.row.col.f32.tf32.tf32.f32 "
        "{%0,%1,%2,%3}, {%4,%5,%6,%7}, {%8,%9}, {%0,%1,%2,%3};"
        : "+f"(c[0]), "+f"(c[1]), "+f"(c[2]), "+f"(c[3])
        : "r"(a[0]), "r"(a[1]), "r"(a[2]), "r"(a[3]), "r"(b[0]), "r"(b[1]));
}

// ---------------------------------------------------------------------------
// tf32 tensor-core GEMM:  C[row, col] = epi( A[M,K] @ BT[N,K]^T + bias )
// CTA tile 128 x BN, BK=32, double-buffered SMEM (pad stride 36 floats).
// 256 threads = 8 warps in 4(m) x 2(n); warp tile 32 x (BN/2).
// grid = (N/BN, M/128). Requires K%32==0, M%128==0, N%BN==0.
// ---------------------------------------------------------------------------
template <int BN>
__global__ __launch_bounds__(256) void mmagemm_k(
    const float* __restrict__ A, const float* __restrict__ BT,
    const float* __restrict__ bias, float* __restrict__ C,
    int K, int ldc, int do_relu)
{
    constexpr int LDP = 36;                 // padded row stride (floats)
    constexpr int ASZ = 128 * LDP;          // one A buffer
    constexpr int BSZ = BN * LDP;           // one B buffer
    constexpr int NT  = BN / 16;            // n-tiles per warp (8 or 4)
    constexpr int NB4 = (BN * 8) / 256;     // B float4 per thread per chunk

    extern __shared__ float sm[];
    float* Abuf[2] = { sm, sm + ASZ };
    float* Bbuf[2] = { sm + 2 * ASZ, sm + 2 * ASZ + BSZ };

    const int tid  = threadIdx.x;
    const int lane = tid & 31;
    const int wid  = tid >> 5;
    const int warpM = (wid & 3) * 32;
    const int warpN = (wid >> 2) * (BN / 2);
    const int rowBase = blockIdx.y * 128;
    const int colBase = blockIdx.x * BN;
    const int qr = lane >> 2, qk = lane & 3;

    float acc[2][NT][4];
#pragma unroll
    for (int mt = 0; mt < 2; mt++)
#pragma unroll
        for (int nt = 0; nt < NT; nt++)
#pragma unroll
            for (int q = 0; q < 4; q++) acc[mt][nt][q] = 0.f;

    float4 stA[4], stB[NB4];

    auto g_load = [&](int k0) {
#pragma unroll
        for (int it = 0; it < 4; it++) {
            int e = it * 256 + tid, r = e >> 3, q = e & 7;
            stA[it] = *(const float4*)(A + (size_t)(rowBase + r) * K + k0 + q * 4);
        }
#pragma unroll
        for (int it = 0; it < NB4; it++) {
            int e = it * 256 + tid, r = e >> 3, q = e & 7;
            stB[it] = *(const float4*)(BT + (size_t)(colBase + r) * K + k0 + q * 4);
        }
    };
    auto s_store = [&](int b) {
#pragma unroll
        for (int it = 0; it < 4; it++) {
            int e = it * 256 + tid, r = e >> 3, q = e & 7;
            float4 v = { f2tf32f(stA[it].x), f2tf32f(stA[it].y),
                         f2tf32f(stA[it].z), f2tf32f(stA[it].w) };
            *(float4*)(Abuf[b] + r * LDP + q * 4) = v;
        }
#pragma unroll
        for (int it = 0; it < NB4; it++) {
            int e = it * 256 + tid, r = e >> 3, q = e & 7;
            float4 v = { f2tf32f(stB[it].x), f2tf32f(stB[it].y),
                         f2tf32f(stB[it].z), f2tf32f(stB[it].w) };
            *(float4*)(Bbuf[b] + r * LDP + q * 4) = v;
        }
    };
    auto compute = [&](int b) {
        const float* Ab = Abuf[b];
        const float* Bb = Bbuf[b];
#pragma unroll
        for (int kk = 0; kk < 4; kk++) {
            uint32_t af[2][4], bf[NT][2];
#pragma unroll
            for (int mt = 0; mt < 2; mt++) {
                int r0 = warpM + mt * 16 + qr;
                af[mt][0] = __float_as_uint(Ab[(r0)     * LDP + kk * 8 + qk]);
                af[mt][1] = __float_as_uint(Ab[(r0 + 8) * LDP + kk * 8 + qk]);
                af[mt][2] = __float_as_uint(Ab[(r0)     * LDP + kk * 8 + qk + 4]);
                af[mt][3] = __float_as_uint(Ab[(r0 + 8) * LDP + kk * 8 + qk + 4]);
            }
#pragma unroll
            for (int nt = 0; nt < NT; nt++) {
                int n0 = warpN + nt * 8 + qr;
                bf[nt][0] = __float_as_uint(Bb[n0 * LDP + kk * 8 + qk]);
                bf[nt][1] = __float_as_uint(Bb[n0 * LDP + kk * 8 + qk + 4]);
            }
#pragma unroll
            for (int mt = 0; mt < 2; mt++)
#pragma unroll
                for (int nt = 0; nt < NT; nt++)
                    mma8(acc[mt][nt], af[mt], bf[nt]);
        }
    };

    const int nc = K >> 5;
    g_load(0);
    s_store(0);
    __syncthreads();
    for (int i = 0; i < nc; i++) {
        if (i + 1 < nc) g_load((i + 1) << 5);
        compute(i & 1);
        if (i + 1 < nc) s_store((i + 1) & 1);
        __syncthreads();
    }

    // epilogue: bias + optional relu, float2 stores
#pragma unroll
    for (int mt = 0; mt < 2; mt++) {
        int row = rowBase + warpM + mt * 16 + qr;
#pragma unroll
        for (int nt = 0; nt < NT; nt++) {
            int col = colBase + warpN + nt * 8 + qk * 2;
            float b0 = bias[col], b1 = bias[col + 1];
            float2 v0 = { acc[mt][nt][0] + b0, acc[mt][nt][1] + b1 };
            float2 v1 = { acc[mt][nt][2] + b0, acc[mt][nt][3] + b1 };
            if (do_relu) {
                v0.x = fmaxf(v0.x, 0.f); v0.y = fmaxf(v0.y, 0.f);
                v1.x = fmaxf(v1.x, 0.f); v1.y = fmaxf(v1.y, 0.f);
            }
            *(float2*)(C + (size_t)row * ldc + col)       = v0;
            *(float2*)(C + (size_t)(row + 8) * ldc + col) = v1;
        }
    }
}

// ---------------------------------------------------------------------------
// Transpose: out[c*K + k] = in[k*N + c]   (K, N multiples of 32)
// ---------------------------------------------------------------------------
__global__ void transpose_k(const float* __restrict__ in, float* __restrict__ out,
                            int K, int N)
{
    __shared__ float t[32][33];
    int k0 = blockIdx.y * 32, c0 = blockIdx.x * 32;
    for (int r = threadIdx.y; r < 32; r += 8)
        t[r][threadIdx.x] = in[(size_t)(k0 + r) * N + c0 + threadIdx.x];
    __syncthreads();
    for (int r = threadIdx.y; r < 32; r += 8)
        out[(size_t)(c0 + r) * K + k0 + threadIdx.x] = t[threadIdx.x][r];
}

// WcatT[c][k]: c<32 -> gc1_W[k,c], else gc3_W[k,c-32]   -> [64,512]
__global__ void concat_wt_k(const float* __restrict__ g1, const float* __restrict__ g3)
{
    int idx = blockIdx.x * 256 + threadIdx.x;   // 64*512
    if (idx < 64 * 512) {
        int c = idx >> 9, k = idx & 511;
        g_WcatT[idx] = (c < 32) ? g1[k * 32 + c] : g3[k * 32 + (c - 32)];
    }
}

// ---------------------------------------------------------------------------
// Per-graph kernel P1: adjacency, branches, z2/z4, omean (known-good)
// ---------------------------------------------------------------------------
__global__ __launch_bounds__(256) void graph_p1_k(
    const float* __restrict__ b1, const float* __restrict__ b3)
{
    const int g = blockIdx.x;
    const int tid = threadIdx.x;

    __shared__ float POOL[16 * 513];
    __shared__ float PS[8 * 16 * 17];
    __shared__ float sA[16 * 17];
    __shared__ float sB[16 * 17];
    __shared__ float rr[16], dv[16], w2s[16], w4s[16], nr[16];

    const float* xg = g_obj + (size_t)g * 8192;
    for (int idx = tid; idx < 8192; idx += 256)
        POOL[(idx >> 9) * 513 + (idx & 511)] = xg[idx];
    __syncthreads();

    for (int c = tid; c < 512; c += 256) {
        float s = 0.f;
#pragma unroll
        for (int d = 0; d < 16; d++) s += POOL[d * 513 + c];
        g_OM[(size_t)g * 512 + c] = s * 0.0625f;
    }

    if (tid < 128) {
        int kc = tid >> 4;
        int tile = tid & 15;
        int ti = (tile >> 2) * 4, tj = (tile & 3) * 4;
        float acc[4][4];
#pragma unroll
        for (int m = 0; m < 4; m++)
#pragma unroll
            for (int n = 0; n < 4; n++) acc[m][n] = 0.f;
        int k0 = kc * 64;
        for (int k = k0; k < k0 + 64; k++) {
            float a0 = POOL[(ti + 0) * 513 + k];
            float a1 = POOL[(ti + 1) * 513 + k];
            float a2 = POOL[(ti + 2) * 513 + k];
            float a3 = POOL[(ti + 3) * 513 + k];
            float b0 = POOL[(tj + 0) * 513 + k];
            float c1 = POOL[(tj + 1) * 513 + k];
            float c2 = POOL[(tj + 2) * 513 + k];
            float c3 = POOL[(tj + 3) * 513 + k];
            acc[0][0] += a0 * b0; acc[0][1] += a0 * c1; acc[0][2] += a0 * c2; acc[0][3] += a0 * c3;
            acc[1][0] += a1 * b0; acc[1][1] += a1 * c1; acc[1][2] += a1 * c2; acc[1][3] += a1 * c3;
            acc[2][0] += a2 * b0; acc[2][1] += a2 * c1; acc[2][2] += a2 * c2; acc[2][3] += a2 * c3;
            acc[3][0] += a3 * b0; acc[3][1] += a3 * c1; acc[3][2] += a3 * c2; acc[3][3] += a3 * c3;
        }
#pragma unroll
        for (int m = 0; m < 4; m++)
#pragma unroll
            for (int n = 0; n < 4; n++)
                PS[kc * 272 + (ti + m) * 17 + (tj + n)] = acc[m][n];
    }
    __syncthreads();

    {
        const float* ttg = g_TT + (size_t)g * 1024;
        for (int idx = tid; idx < 1024; idx += 256) {
            int r = idx >> 6, c = idx & 63;
            float v = ttg[idx];
            if (c < 32) POOL[r * 33 + c] = v;
            else        POOL[528 + r * 33 + (c - 32)] = v;
        }
    }
    {
        int i = tid >> 4, j = tid & 15;
        float s = 0.f;
#pragma unroll
        for (int kc = 0; kc < 8; kc++) s += PS[kc * 272 + i * 17 + j];
        sA[i * 17 + j] = s;
    }
    __syncthreads();

    if (tid < 16) {
        float m = -3.4e38f;
        for (int j = 0; j < 16; j++) m = fmaxf(m, sA[tid * 17 + j]);
        rr[tid] = m;
    }
    __syncthreads();
    { int i = tid >> 4, j = tid & 15; sA[i * 17 + j] = expf(sA[i * 17 + j] - rr[i]); }
    __syncthreads();
    if (tid < 16) {
        float s = 0.f;
        for (int j = 0; j < 16; j++) s += sA[tid * 17 + j];
        dv[tid] = rsqrtf(s);
    }
    __syncthreads();
    { int i = tid >> 4, j = tid & 15; sA[i * 17 + j] *= dv[i] * dv[j]; }
    __syncthreads();

    if (tid < 16) {
        float s = 0.f;
        for (int i = 0; i < 16; i++) s += sA[i * 17 + tid];
        w2s[tid] = s * 0.0625f;
    }
    for (int o = tid; o < 1024; o += 256) {
        int which = o >> 9, r = (o >> 5) & 15, c = o & 31;
        const float* Ts = which ? (POOL + 528) : POOL;
        float acc = which ? b3[c] : b1[c];
#pragma unroll
        for (int j = 0; j < 16; j++) acc += sA[r * 17 + j] * Ts[j * 33 + c];
        acc = fmaxf(acc, 0.f);
        (which ? (POOL + 1584) : (POOL + 1056))[r * 33 + c] = acc;
    }
    __syncthreads();

    {
        int i = tid >> 4, j = tid & 15;
        const float* Y2S = POOL + 1584;
        float acc = 0.f;
#pragma unroll
        for (int k = 0; k < 32; k++) acc += Y2S[i * 33 + k] * Y2S[j * 33 + k];
        sB[i * 17 + j] = acc;
    }
    __syncthreads();
    if (tid < 16) {
        float s = 0.f;
        for (int j = 0; j < 16; j++) { float v = sB[tid * 17 + j]; s += v * v; }
        nr[tid] = sqrtf(s);
    }
    __syncthreads();
    { int i = tid >> 4, j = tid & 15; sB[i * 17 + j] = 1.f + sB[i * 17 + j] / (nr[i] * nr[j]); }
    __syncthreads();
    if (tid < 16) {
        float s = 0.f;
        for (int j = 0; j < 16; j++) s += sB[tid * 17 + j];
        dv[tid] = rsqrtf(s);
    }
    __syncthreads();
    { int i = tid >> 4, j = tid & 15; sB[i * 17 + j] *= dv[i] * dv[j]; }
    __syncthreads();
    if (tid < 16) {
        float s = 0.f;
        for (int i = 0; i < 16; i++) s += sB[i * 17 + tid];
        w4s[tid] = s * 0.0625f;
    }
    __syncthreads();

    if (tid < 64) {
        int which = tid >> 5, c = tid & 31;
        const float* V = which ? (POOL + 1584) : (POOL + 1056);
        const float* w = which ? w4s : w2s;
        float acc = 0.f;
#pragma unroll
        for (int j = 0; j < 16; j++) acc += w[j] * V[j * 33 + c];
        g_Z[(size_t)g * 64 + tid] = acc;
    }
}

// ---------------------------------------------------------------------------
// P2: h = relu(0.5*omean + 0.25*(z2@gc2_W + z4@gc4_W + b2 + b4))
// ---------------------------------------------------------------------------
__global__ __launch_bounds__(512) void graph_p2_k(
    const float* __restrict__ gc2_W, const float* __restrict__ b2,
    const float* __restrict__ gc4_W, const float* __restrict__ b4)
{
    const int g0 = blockIdx.x * 8;
    const int tid = threadIdx.x;
    __shared__ float zs[8][64];
    zs[tid >> 6][tid & 63] = g_Z[(size_t)g0 * 64 + tid];
    __syncthreads();

    const int c = tid;
    float acc[8];
    float base = b2[c] + b4[c];
#pragma unroll
    for (int gg = 0; gg < 8; gg++) acc[gg] = base;
#pragma unroll
    for (int k = 0; k < 32; k++) {
        float w = gc2_W[k * 512 + c];
#pragma unroll
        for (int gg = 0; gg < 8; gg++) acc[gg] += zs[gg][k] * w;
    }
#pragma unroll
    for (int k = 0; k < 32; k++) {
        float w = gc4_W[k * 512 + c];
#pragma unroll
        for (int gg = 0; gg < 8; gg++) acc[gg] += zs[gg][32 + k] * w;
    }
#pragma unroll
    for (int gg = 0; gg < 8; gg++) {
        float h = 0.5f * g_OM[(size_t)(g0 + gg) * 512 + c] + 0.25f * acc[gg];
        g_H[(size_t)(g0 + gg) * 512 + c] = fmaxf(h, 0.f);
    }
}

__global__ void reduce_t_k()
{
    int n = blockIdx.x;
    int c = blockIdx.y * 256 + threadIdx.x;
    const float* p = g_C + (size_t)n * 64 * 1024 + c;
    float s = 0.f;
#pragma unroll
    for (int t = 0; t < 64; t++) s += p[t * 1024];
    g_CB[n * 1024 + c] = s * (1.f / 64.f);
}

__global__ __launch_bounds__(512) void clf_k(
    const float* __restrict__ W, const float* __restrict__ b,
    float* __restrict__ out)
{
    int n = blockIdx.x;
    int tid = threadIdx.x;
    __shared__ float cb[1024];
    cb[tid]       = g_CB[n * 1024 + tid];
    cb[tid + 512] = g_CB[n * 1024 + tid + 512];
    __syncthreads();
    if (tid < 500) {
        float acc = b[tid];
        for (int k = 0; k < 1024; k++) acc += cb[k] * W[k * 500 + tid];
        out[n * 500 + tid] = acc;
    }
}

// ---------------------------------------------------------------------------
// kernel_launch
// ---------------------------------------------------------------------------
extern "C" void kernel_launch(void* const* d_in, const int* in_sizes, int n_in,
                              void* d_out, int out_size)
{
    const float* object_raw = (const float*)d_in[0];
    const float* action_raw = (const float*)d_in[1];
    const float* W_obj = (const float*)d_in[2];
    const float* b_obj = (const float*)d_in[3];
    const float* W_act = (const float*)d_in[4];
    const float* b_act = (const float*)d_in[5];
    const float* gc1_W = (const float*)d_in[6];
    const float* gc1_b = (const float*)d_in[7];
    const float* gc2_W = (const float*)d_in[8];
    const float* gc2_b = (const float*)d_in[9];
    const float* gc3_W = (const float*)d_in[10];
    const float* gc3_b = (const float*)d_in[11];
    const float* gc4_W = (const float*)d_in[12];
    const float* gc4_b = (const float*)d_in[13];
    const float* fc1_W = (const float*)d_in[14];
    const float* fc1_b = (const float*)d_in[15];
    const float* clf_W = (const float*)d_in[16];
    const float* clf_b = (const float*)d_in[17];
    float* out = (float*)d_out;

    float *p_obj, *p_TT, *p_H, *p_C, *p_zero;
    float *p_WobjT, *p_WactT, *p_fc1T, *p_WcatT;
    cudaGetSymbolAddress((void**)&p_obj,   g_obj);
    cudaGetSymbolAddress((void**)&p_TT,    g_TT);
    cudaGetSymbolAddress((void**)&p_H,     g_H);
    cudaGetSymbolAddress((void**)&p_C,     g_C);
    cudaGetSymbolAddress((void**)&p_zero,  g_zero64);
    cudaGetSymbolAddress((void**)&p_WobjT, g_WobjT);
    cudaGetSymbolAddress((void**)&p_WactT, g_WactT);
    cudaGetSymbolAddress((void**)&p_fc1T,  g_fc1T);
    cudaGetSymbolAddress((void**)&p_WcatT, g_WcatT);

    // dynamic SMEM: 2 * (128*36 + BN*36) * 4 bytes
    const int SZ128 = 2 * (128 * 36 + 128 * 36) * 4;   // 73728
    const int SZ64  = 2 * (128 * 36 +  64 * 36) * 4;   // 55296
    cudaFuncSetAttribute(mmagemm_k<128>, cudaFuncAttributeMaxDynamicSharedMemorySize, SZ128);
    cudaFuncSetAttribute(mmagemm_k<64>,  cudaFuncAttributeMaxDynamicSharedMemorySize, SZ64);

    // 0) weight transposes (B operands must be [N, K])
    transpose_k<<<dim3(512 / 32, 512 / 32), dim3(32, 8)>>>(W_obj, p_WobjT, 512, 512);
    transpose_k<<<dim3(512 / 32, 512 / 32), dim3(32, 8)>>>(W_act, p_WactT, 512, 512);
    transpose_k<<<dim3(1024 / 32, 512 / 32), dim3(32, 8)>>>(fc1_W, p_fc1T, 512, 1024);
    concat_wt_k<<<(64 * 512 + 255) / 256, 256>>>(gc1_W, gc3_W);

    // 1) obj = relu(object_raw @ W_obj + b_obj)   [32768, 512]
    mmagemm_k<128><<<dim3(4, M0 / 128), 256, SZ128>>>(
        object_raw, p_WobjT, b_obj, p_obj, 512, 512, 1);

    // 2) act = relu(action_raw @ W_act + b_act) -> obj rows 16g+8 (ldc=8192)
    mmagemm_k<128><<<dim3(4, 16), 256, SZ128>>>(
        action_raw, p_WactT, b_act, p_obj + 8 * 512, 512, 16 * 512, 1);

    // 3) TT = obj @ [gc1_W | gc3_W]   [32768, 64]
    mmagemm_k<64><<<dim3(1, M0 / 128), 256, SZ64>>>(
        p_obj, p_WcatT, p_zero, p_TT, 512, 64, 0);

    // 4) per-graph adjacency / branches / z / omean
    graph_p1_k<<<GNUM, 256>>>(gc1_b, gc3_b);

    // 5) h = relu(feat)
    graph_p2_k<<<GNUM / 8, 512>>>(gc2_W, gc2_b, gc4_W, gc4_b);

    // 6) c = relu(h @ fc1_W + fc1_b)   [2048, 1024]
    mmagemm_k<128><<<dim3(8, 16), 256, SZ128>>>(
        p_H, p_fc1T, fc1_b, p_C, 512, 1024, 1);

    // 7) mean over T, 8) classifier
    reduce_t_k<<<dim3(32, 4), 256>>>();
    clf_k<<<32, 512>>>(clf_W, clf_b, out);
}

// round 17
// speedup vs baseline: 2.3647x; 1.2615x over previous
#include <cuda_runtime.h>
#include <cstdint>

// ---------------------------------------------------------------------------
// Problem constants: N=32, T=64, D=16, F=512 ; obj rows M0=32768, graphs=2048
// ---------------------------------------------------------------------------
#define M0 32768
#define GNUM 2048

// Scratch (device globals; allocation-free)
__device__ float g_obj[32768 * 512];
__device__ float g_TT [32768 * 64];
__device__ float g_Z  [2048 * 64];
__device__ float g_OM [2048 * 512];
__device__ float g_H  [2048 * 512];
__device__ float g_C  [2048 * 1024];
__device__ float g_CB [32 * 1024];
__device__ float g_zero64[64];
// transposed weights (B operands are [N, K] k-major), pre-rounded to tf32
__device__ float g_WobjT[512 * 512];
__device__ float g_WactT[512 * 512];
__device__ float g_fc1T [1024 * 512];
__device__ float g_WcatT[64 * 512];

// ---------------------------------------------------------------------------
// tf32 helpers (legacy tensor-core path: mma.sync, valid on plain sm_103)
// ---------------------------------------------------------------------------
__device__ __forceinline__ float f2tf32f(float x) {
    uint32_t u; asm("cvt.rna.tf32.f32 %0, %1;" : "=r"(u) : "f"(x));
    return __uint_as_float(u);
}
__device__ __forceinline__ void mma8(float* c, const uint32_t* a, const uint32_t* b) {
    asm volatile(
        "mma.sync.aligned.m16n8k8.row.col.f32.tf32.tf32.f32 "
        "{%0,%1,%2,%3}, {%4,%5,%6,%7}, {%8,%9}, {%0,%1,%2,%3};"
        : "+f"(c[0]), "+f"(c[1]), "+f"(c[2]), "+f"(c[3])
        : "r"(a[0]), "r"(a[1]), "r"(a[2]), "r"(a[3]), "r"(b[0]), "r"(b[1]));
}
__device__ __forceinline__ uint32_t smem_u32(const void* p) {
    uint32_t a;
    asm("{ .reg .u64 t; cvta.to.shared.u64 t, %1; cvt.u32.u64 %0, t; }"
        : "=r"(a) : "l"(p));
    return a;
}
__device__ __forceinline__ void cp16(uint32_t s, const void* g) {
    asm volatile("cp.async.cg.shared.global [%0], [%1], 16;" :: "r"(s), "l"(g) : "memory");
}
#define CP_COMMIT() asm volatile("cp.async.commit_group;" ::: "memory")
#define CP_WAIT0()  asm volatile("cp.async.wait_group 0;" ::: "memory")

// ---------------------------------------------------------------------------
// tf32 tensor-core GEMM:  C[row, col] = epi( A[M,K] @ BT[N,K]^T + bias )
// CTA tile 128 x BN, BK=32, double-buffered SMEM (pad stride 36 floats).
// A: LDG->reg->cvt->STS staging. B: pre-rounded in gmem, cp.async direct.
// 256 threads = 8 warps in 4(m) x 2(n); warp tile 32 x (BN/2).
// Optional fused second problem: blocks with blockIdx.y >= yMain use
// (A2, BT2, bias2, C2, ldc2) with rebased row index.
// ---------------------------------------------------------------------------
template <int BN>
__global__ __launch_bounds__(256, 2) void mmagemm_k(
    const float* __restrict__ A, const float* __restrict__ BT,
    const float* __restrict__ bias, float* __restrict__ C,
    int K, int ldc, int do_relu, int yMain,
    const float* __restrict__ A2, const float* __restrict__ BT2,
    const float* __restrict__ bias2, float* __restrict__ C2, int ldc2)
{
    constexpr int LDP = 36;                 // padded row stride (floats)
    constexpr int ASZ = 128 * LDP;          // one A buffer
    constexpr int BSZ = BN * LDP;           // one B buffer
    constexpr int NT  = BN / 16;            // n-tiles per warp (8 or 4)
    constexpr int NB4 = (BN * 8) / 256;     // B float4 per thread per chunk

    extern __shared__ float sm[];
    float* Abuf[2] = { sm, sm + ASZ };
    float* Bbuf[2] = { sm + 2 * ASZ, sm + 2 * ASZ + BSZ };

    int by = blockIdx.y;
    if (by >= yMain) {            // fused secondary problem
        A = A2; BT = BT2; bias = bias2; C = C2; ldc = ldc2;
        by -= yMain;
    }

    const int tid  = threadIdx.x;
    const int lane = tid & 31;
    const int wid  = tid >> 5;
    const int warpM = (wid & 3) * 32;
    const int warpN = (wid >> 2) * (BN / 2);
    const int rowBase = by * 128;
    const int colBase = blockIdx.x * BN;
    const int qr = lane >> 2, qk = lane & 3;

    const uint32_t bB[2] = { smem_u32(Bbuf[0]), smem_u32(Bbuf[1]) };

    float acc[2][NT][4];
#pragma unroll
    for (int mt = 0; mt < 2; mt++)
#pragma unroll
        for (int nt = 0; nt < NT; nt++)
#pragma unroll
            for (int q = 0; q < 4; q++) acc[mt][nt][q] = 0.f;

    float4 stA[4];

    auto b_issue = [&](int b, int k0) {
#pragma unroll
        for (int it = 0; it < NB4; it++) {
            int e = it * 256 + tid, r = e >> 3, q = e & 7;
            cp16(bB[b] + (uint32_t)(r * LDP + q * 4) * 4u,
                 BT + (size_t)(colBase + r) * K + k0 + q * 4);
        }
        CP_COMMIT();
    };
    auto a_load = [&](int k0) {
#pragma unroll
        for (int it = 0; it < 4; it++) {
            int e = it * 256 + tid, r = e >> 3, q = e & 7;
            stA[it] = *(const float4*)(A + (size_t)(rowBase + r) * K + k0 + q * 4);
        }
    };
    auto a_store = [&](int b) {
#pragma unroll
        for (int it = 0; it < 4; it++) {
            int e = it * 256 + tid, r = e >> 3, q = e & 7;
            float4 v = { f2tf32f(stA[it].x), f2tf32f(stA[it].y),
                         f2tf32f(stA[it].z), f2tf32f(stA[it].w) };
            *(float4*)(Abuf[b] + r * LDP + q * 4) = v;
        }
    };
    auto compute = [&](int b) {
        const float* Ab = Abuf[b];
        const float* Bb = Bbuf[b];
#pragma unroll
        for (int kk = 0; kk < 4; kk++) {
            uint32_t af[2][4], bf[NT][2];
#pragma unroll
            for (int mt = 0; mt < 2; mt++) {
                int r0 = warpM + mt * 16 + qr;
                af[mt][0] = __float_as_uint(Ab[(r0)     * LDP + kk * 8 + qk]);
                af[mt][1] = __float_as_uint(Ab[(r0 + 8) * LDP + kk * 8 + qk]);
                af[mt][2] = __float_as_uint(Ab[(r0)     * LDP + kk * 8 + qk + 4]);
                af[mt][3] = __float_as_uint(Ab[(r0 + 8) * LDP + kk * 8 + qk + 4]);
            }
#pragma unroll
            for (int nt = 0; nt < NT; nt++) {
                int n0 = warpN + nt * 8 + qr;
                bf[nt][0] = __float_as_uint(Bb[n0 * LDP + kk * 8 + qk]);
                bf[nt][1] = __float_as_uint(Bb[n0 * LDP + kk * 8 + qk + 4]);
            }
#pragma unroll
            for (int mt = 0; mt < 2; mt++)
#pragma unroll
                for (int nt = 0; nt < NT; nt++)
                    mma8(acc[mt][nt], af[mt], bf[nt]);
        }
    };

    const int nc = K >> 5;
    b_issue(0, 0);
    a_load(0);
    a_store(0);
    CP_WAIT0();
    __syncthreads();
    for (int i = 0; i < nc; i++) {
        if (i + 1 < nc) {
            b_issue((i + 1) & 1, (i + 1) << 5);
            a_load((i + 1) << 5);
        }
        compute(i & 1);
        if (i + 1 < nc) a_store((i + 1) & 1);
        CP_WAIT0();
        __syncthreads();
    }

    // epilogue: bias + optional relu, float2 stores
#pragma unroll
    for (int mt = 0; mt < 2; mt++) {
        int row = rowBase + warpM + mt * 16 + qr;
#pragma unroll
        for (int nt = 0; nt < NT; nt++) {
            int col = colBase + warpN + nt * 8 + qk * 2;
            float b0 = bias[col], b1 = bias[col + 1];
            float2 v0 = { acc[mt][nt][0] + b0, acc[mt][nt][1] + b1 };
            float2 v1 = { acc[mt][nt][2] + b0, acc[mt][nt][3] + b1 };
            if (do_relu) {
                v0.x = fmaxf(v0.x, 0.f); v0.y = fmaxf(v0.y, 0.f);
                v1.x = fmaxf(v1.x, 0.f); v1.y = fmaxf(v1.y, 0.f);
            }
            *(float2*)(C + (size_t)row * ldc + col)       = v0;
            *(float2*)(C + (size_t)(row + 8) * ldc + col) = v1;
        }
    }
}

// ---------------------------------------------------------------------------
// Transpose + tf32 round: out[c*K + k] = tf32(in[k*N + c])
// ---------------------------------------------------------------------------
__global__ void transpose_k(const float* __restrict__ in, float* __restrict__ out,
                            int K, int N)
{
    __shared__ float t[32][33];
    int k0 = blockIdx.y * 32, c0 = blockIdx.x * 32;
    for (int r = threadIdx.y; r < 32; r += 8)
        t[r][threadIdx.x] = in[(size_t)(k0 + r) * N + c0 + threadIdx.x];
    __syncthreads();
    for (int r = threadIdx.y; r < 32; r += 8)
        out[(size_t)(c0 + r) * K + k0 + threadIdx.x] = f2tf32f(t[threadIdx.x][r]);
}

// WcatT[c][k] (tf32-rounded): c<32 -> gc1_W[k,c], else gc3_W[k,c-32]
__global__ void concat_wt_k(const float* __restrict__ g1, const float* __restrict__ g3)
{
    int idx = blockIdx.x * 256 + threadIdx.x;   // 64*512
    if (idx < 64 * 512) {
        int c = idx >> 9, k = idx & 511;
        g_WcatT[idx] = f2tf32f((c < 32) ? g1[k * 32 + c] : g3[k * 32 + (c - 32)]);
    }
}

// ---------------------------------------------------------------------------
// Per-graph kernel P1: adjacency, branches, z2/z4, omean (known-good)
// ---------------------------------------------------------------------------
__global__ __launch_bounds__(256) void graph_p1_k(
    const float* __restrict__ b1, const float* __restrict__ b3)
{
    const int g = blockIdx.x;
    const int tid = threadIdx.x;

    __shared__ float POOL[16 * 513];
    __shared__ float PS[8 * 16 * 17];
    __shared__ float sA[16 * 17];
    __shared__ float sB[16 * 17];
    __shared__ float rr[16], dv[16], w2s[16], w4s[16], nr[16];

    const float* xg = g_obj + (size_t)g * 8192;
    for (int idx = tid; idx < 8192; idx += 256)
        POOL[(idx >> 9) * 513 + (idx & 511)] = xg[idx];
    __syncthreads();

    for (int c = tid; c < 512; c += 256) {
        float s = 0.f;
#pragma unroll
        for (int d = 0; d < 16; d++) s += POOL[d * 513 + c];
        g_OM[(size_t)g * 512 + c] = s * 0.0625f;
    }

    if (tid < 128) {
        int kc = tid >> 4;
        int tile = tid & 15;
        int ti = (tile >> 2) * 4, tj = (tile & 3) * 4;
        float acc[4][4];
#pragma unroll
        for (int m = 0; m < 4; m++)
#pragma unroll
            for (int n = 0; n < 4; n++) acc[m][n] = 0.f;
        int k0 = kc * 64;
        for (int k = k0; k < k0 + 64; k++) {
            float a0 = POOL[(ti + 0) * 513 + k];
            float a1 = POOL[(ti + 1) * 513 + k];
            float a2 = POOL[(ti + 2) * 513 + k];
            float a3 = POOL[(ti + 3) * 513 + k];
            float b0 = POOL[(tj + 0) * 513 + k];
            float c1 = POOL[(tj + 1) * 513 + k];
            float c2 = POOL[(tj + 2) * 513 + k];
            float c3 = POOL[(tj + 3) * 513 + k];
            acc[0][0] += a0 * b0; acc[0][1] += a0 * c1; acc[0][2] += a0 * c2; acc[0][3] += a0 * c3;
            acc[1][0] += a1 * b0; acc[1][1] += a1 * c1; acc[1][2] += a1 * c2; acc[1][3] += a1 * c3;
            acc[2][0] += a2 * b0; acc[2][1] += a2 * c1; acc[2][2] += a2 * c2; acc[2][3] += a2 * c3;
            acc[3][0] += a3 * b0; acc[3][1] += a3 * c1; acc[3][2] += a3 * c2; acc[3][3] += a3 * c3;
        }
#pragma unroll
        for (int m = 0; m < 4; m++)
#pragma unroll
            for (int n = 0; n < 4; n++)
                PS[kc * 272 + (ti + m) * 17 + (tj + n)] = acc[m][n];
    }
    __syncthreads();

    {
        const float* ttg = g_TT + (size_t)g * 1024;
        for (int idx = tid; idx < 1024; idx += 256) {
            int r = idx >> 6, c = idx & 63;
            float v = ttg[idx];
            if (c < 32) POOL[r * 33 + c] = v;
            else        POOL[528 + r * 33 + (c - 32)] = v;
        }
    }
    {
        int i = tid >> 4, j = tid & 15;
        float s = 0.f;
#pragma unroll
        for (int kc = 0; kc < 8; kc++) s += PS[kc * 272 + i * 17 + j];
        sA[i * 17 + j] = s;
    }
    __syncthreads();

    if (tid < 16) {
        float m = -3.4e38f;
        for (int j = 0; j < 16; j++) m = fmaxf(m, sA[tid * 17 + j]);
        rr[tid] = m;
    }
    __syncthreads();
    { int i = tid >> 4, j = tid & 15; sA[i * 17 + j] = expf(sA[i * 17 + j] - rr[i]); }
    __syncthreads();
    if (tid < 16) {
        float s = 0.f;
        for (int j = 0; j < 16; j++) s += sA[tid * 17 + j];
        dv[tid] = rsqrtf(s);
    }
    __syncthreads();
    { int i = tid >> 4, j = tid & 15; sA[i * 17 + j] *= dv[i] * dv[j]; }
    __syncthreads();

    if (tid < 16) {
        float s = 0.f;
        for (int i = 0; i < 16; i++) s += sA[i * 17 + tid];
        w2s[tid] = s * 0.0625f;
    }
    for (int o = tid; o < 1024; o += 256) {
        int which = o >> 9, r = (o >> 5) & 15, c = o & 31;
        const float* Ts = which ? (POOL + 528) : POOL;
        float acc = which ? b3[c] : b1[c];
#pragma unroll
        for (int j = 0; j < 16; j++) acc += sA[r * 17 + j] * Ts[j * 33 + c];
        acc = fmaxf(acc, 0.f);
        (which ? (POOL + 1584) : (POOL + 1056))[r * 33 + c] = acc;
    }
    __syncthreads();

    {
        int i = tid >> 4, j = tid & 15;
        const float* Y2S = POOL + 1584;
        float acc = 0.f;
#pragma unroll
        for (int k = 0; k < 32; k++) acc += Y2S[i * 33 + k] * Y2S[j * 33 + k];
        sB[i * 17 + j] = acc;
    }
    __syncthreads();
    if (tid < 16) {
        float s = 0.f;
        for (int j = 0; j < 16; j++) { float v = sB[tid * 17 + j]; s += v * v; }
        nr[tid] = sqrtf(s);
    }
    __syncthreads();
    { int i = tid >> 4, j = tid & 15; sB[i * 17 + j] = 1.f + sB[i * 17 + j] / (nr[i] * nr[j]); }
    __syncthreads();
    if (tid < 16) {
        float s = 0.f;
        for (int j = 0; j < 16; j++) s += sB[tid * 17 + j];
        dv[tid] = rsqrtf(s);
    }
    __syncthreads();
    { int i = tid >> 4, j = tid & 15; sB[i * 17 + j] *= dv[i] * dv[j]; }
    __syncthreads();
    if (tid < 16) {
        float s = 0.f;
        for (int i = 0; i < 16; i++) s += sB[i * 17 + tid];
        w4s[tid] = s * 0.0625f;
    }
    __syncthreads();

    if (tid < 64) {
        int which = tid >> 5, c = tid & 31;
        const float* V = which ? (POOL + 1584) : (POOL + 1056);
        const float* w = which ? w4s : w2s;
        float acc = 0.f;
#pragma unroll
        for (int j = 0; j < 16; j++) acc += w[j] * V[j * 33 + c];
        g_Z[(size_t)g * 64 + tid] = acc;
    }
}

// ---------------------------------------------------------------------------
// P2: h = relu(0.5*omean + 0.25*(z2@gc2_W + z4@gc4_W + b2 + b4))
// ---------------------------------------------------------------------------
__global__ __launch_bounds__(512) void graph_p2_k(
    const float* __restrict__ gc2_W, const float* __restrict__ b2,
    const float* __restrict__ gc4_W, const float* __restrict__ b4)
{
    const int g0 = blockIdx.x * 8;
    const int tid = threadIdx.x;
    __shared__ float zs[8][64];
    zs[tid >> 6][tid & 63] = g_Z[(size_t)g0 * 64 + tid];
    __syncthreads();

    const int c = tid;
    float acc[8];
    float base = b2[c] + b4[c];
#pragma unroll
    for (int gg = 0; gg < 8; gg++) acc[gg] = base;
#pragma unroll
    for (int k = 0; k < 32; k++) {
        float w = gc2_W[k * 512 + c];
#pragma unroll
        for (int gg = 0; gg < 8; gg++) acc[gg] += zs[gg][k] * w;
    }
#pragma unroll
    for (int k = 0; k < 32; k++) {
        float w = gc4_W[k * 512 + c];
#pragma unroll
        for (int gg = 0; gg < 8; gg++) acc[gg] += zs[gg][32 + k] * w;
    }
#pragma unroll
    for (int gg = 0; gg < 8; gg++) {
        float h = 0.5f * g_OM[(size_t)(g0 + gg) * 512 + c] + 0.25f * acc[gg];
        g_H[(size_t)(g0 + gg) * 512 + c] = fmaxf(h, 0.f);
    }
}

__global__ void reduce_t_k()
{
    int n = blockIdx.x;
    int c = blockIdx.y * 256 + threadIdx.x;
    const float* p = g_C + (size_t)n * 64 * 1024 + c;
    float s = 0.f;
#pragma unroll
    for (int t = 0; t < 64; t++) s += p[t * 1024];
    g_CB[n * 1024 + c] = s * (1.f / 64.f);
}

__global__ __launch_bounds__(512) void clf_k(
    const float* __restrict__ W, const float* __restrict__ b,
    float* __restrict__ out)
{
    int n = blockIdx.x;
    int tid = threadIdx.x;
    __shared__ float cb[1024];
    cb[tid]       = g_CB[n * 1024 + tid];
    cb[tid + 512] = g_CB[n * 1024 + tid + 512];
    __syncthreads();
    if (tid < 500) {
        float acc = b[tid];
        for (int k = 0; k < 1024; k++) acc += cb[k] * W[k * 500 + tid];
        out[n * 500 + tid] = acc;
    }
}

// ---------------------------------------------------------------------------
// kernel_launch
// ---------------------------------------------------------------------------
extern "C" void kernel_launch(void* const* d_in, const int* in_sizes, int n_in,
                              void* d_out, int out_size)
{
    const float* object_raw = (const float*)d_in[0];
    const float* action_raw = (const float*)d_in[1];
    const float* W_obj = (const float*)d_in[2];
    const float* b_obj = (const float*)d_in[3];
    const float* W_act = (const float*)d_in[4];
    const float* b_act = (const float*)d_in[5];
    const float* gc1_W = (const float*)d_in[6];
    const float* gc1_b = (const float*)d_in[7];
    const float* gc2_W = (const float*)d_in[8];
    const float* gc2_b = (const float*)d_in[9];
    const float* gc3_W = (const float*)d_in[10];
    const float* gc3_b = (const float*)d_in[11];
    const float* gc4_W = (const float*)d_in[12];
    const float* gc4_b = (const float*)d_in[13];
    const float* fc1_W = (const float*)d_in[14];
    const float* fc1_b = (const float*)d_in[15];
    const float* clf_W = (const float*)d_in[16];
    const float* clf_b = (const float*)d_in[17];
    float* out = (float*)d_out;

    float *p_obj, *p_TT, *p_H, *p_C, *p_zero;
    float *p_WobjT, *p_WactT, *p_fc1T, *p_WcatT;
    cudaGetSymbolAddress((void**)&p_obj,   g_obj);
    cudaGetSymbolAddress((void**)&p_TT,    g_TT);
    cudaGetSymbolAddress((void**)&p_H,     g_H);
    cudaGetSymbolAddress((void**)&p_C,     g_C);
    cudaGetSymbolAddress((void**)&p_zero,  g_zero64);
    cudaGetSymbolAddress((void**)&p_WobjT, g_WobjT);
    cudaGetSymbolAddress((void**)&p_WactT, g_WactT);
    cudaGetSymbolAddress((void**)&p_fc1T,  g_fc1T);
    cudaGetSymbolAddress((void**)&p_WcatT, g_WcatT);

    // dynamic SMEM: 2 * (128*36 + BN*36) * 4 bytes
    const int SZ128 = 2 * (128 * 36 + 128 * 36) * 4;   // 73728
    const int SZ64  = 2 * (128 * 36 +  64 * 36) * 4;   // 55296
    cudaFuncSetAttribute(mmagemm_k<128>, cudaFuncAttributeMaxDynamicSharedMemorySize, SZ128);
    cudaFuncSetAttribute(mmagemm_k<64>,  cudaFuncAttributeMaxDynamicSharedMemorySize, SZ64);

    // 0) weight transposes + tf32 pre-rounding (B operands are [N, K])
    transpose_k<<<dim3(512 / 32, 512 / 32), dim3(32, 8)>>>(W_obj, p_WobjT, 512, 512);
    transpose_k<<<dim3(512 / 32, 512 / 32), dim3(32, 8)>>>(W_act, p_WactT, 512, 512);
    transpose_k<<<dim3(1024 / 32, 512 / 32), dim3(32, 8)>>>(fc1_W, p_fc1T, 512, 1024);
    concat_wt_k<<<(64 * 512 + 255) / 256, 256>>>(gc1_W, gc3_W);

    // 1+2) fused: obj = relu(object_raw @ W_obj + b_obj)  [32768, 512]
    //             act = relu(action_raw @ W_act + b_act) -> obj rows 16g+8
    mmagemm_k<128><<<dim3(4, 256 + 16), 256, SZ128>>>(
        object_raw, p_WobjT, b_obj, p_obj, 512, 512, 1,
        /*yMain=*/256,
        action_raw, p_WactT, b_act, p_obj + 8 * 512, 16 * 512);

    // 3) TT = obj @ [gc1_W | gc3_W]   [32768, 64]
    mmagemm_k<64><<<dim3(1, M0 / 128), 256, SZ64>>>(
        p_obj, p_WcatT, p_zero, p_TT, 512, 64, 0,
        /*yMain=*/1 << 30, nullptr, nullptr, nullptr, nullptr, 0);

    // 4) per-graph adjacency / branches / z / omean
    graph_p1_k<<<GNUM, 256>>>(gc1_b, gc3_b);

    // 5) h = relu(feat)
    graph_p2_k<<<GNUM / 8, 512>>>(gc2_W, gc2_b, gc4_W, gc4_b);

    // 6) c = relu(h @ fc1_W + fc1_b)   [2048, 1024]
    mmagemm_k<128><<<dim3(8, 16), 256, SZ128>>>(
        p_H, p_fc1T, fc1_b, p_C, 512, 1024, 1,
        /*yMain=*/1 << 30, nullptr, nullptr, nullptr, nullptr, 0);

    // 7) mean over T, 8) classifier
    reduce_t_k<<<dim3(32, 4), 256>>>();
    clf_k<<<32, 512>>>(clf_W, clf_b, out);
}